// round 16
// baseline (speedup 1.0000x reference)
#include <cuda_runtime.h>
#include <cuda_fp16.h>
#include <cstdint>

#define HID 4096
#define MROWS 2048
#define NKV 512
#define VECD 64
#define NHEAD 16
#define NBH 64
#define SDUP 2048

// ---------------- scratch ----------------
__device__ __half g_attnT[NBH * SDUP * VECD];
__device__ __half g_qhi[NBH * SDUP * VECD];
__device__ __half g_khi[NBH * NKV * VECD];
__device__ __half g_vhi[NBH * VECD * NKV];
__device__ __half g_ehi[MROWS * HID];
__device__ __half g_lnhi[MROWS * HID];
__device__ __half g_wqp[HID * HID];
__device__ __half g_wrehi[HID * HID];

// ---------------- PTX helpers ----------------
__device__ __forceinline__ uint32_t smem_u32(const void* p) {
    uint32_t a;
    asm("{ .reg .u64 t; cvta.to.shared.u64 t, %1; cvt.u32.u64 %0, t; }" : "=r"(a) : "l"(p));
    return a;
}
#define CP_ASYNC16(dst, src) \
    asm volatile("cp.async.cg.shared.global [%0], [%1], 16;" :: "r"(dst), "l"(src))
#define CP_COMMIT() asm volatile("cp.async.commit_group;" ::: "memory")
#define CP_WAIT0()  asm volatile("cp.async.wait_group 0;" ::: "memory")
#define CP_WAIT1()  asm volatile("cp.async.wait_group 1;" ::: "memory")

#define LDSM4(r0, r1, r2, r3, addr)                                          \
    asm volatile("ldmatrix.sync.aligned.m8n8.x4.shared.b16 {%0,%1,%2,%3}, [%4];" \
                 : "=r"(r0), "=r"(r1), "=r"(r2), "=r"(r3) : "r"(addr))
#define LDSM2(r0, r1, addr)                                                  \
    asm volatile("ldmatrix.sync.aligned.m8n8.x2.shared.b16 {%0,%1}, [%2];"   \
                 : "=r"(r0), "=r"(r1) : "r"(addr))

__device__ __forceinline__ void mma16816h(float* c, const uint32_t* a, const uint32_t* b) {
    asm volatile(
        "mma.sync.aligned.m16n8k16.row.col.f32.f16.f16.f32 "
        "{%0,%1,%2,%3}, {%4,%5,%6,%7}, {%8,%9}, {%0,%1,%2,%3};"
        : "+f"(c[0]), "+f"(c[1]), "+f"(c[2]), "+f"(c[3])
        : "r"(a[0]), "r"(a[1]), "r"(a[2]), "r"(a[3]), "r"(b[0]), "r"(b[1]));
}

__device__ __forceinline__ uint32_t pack_h2(float a, float b) {
    __half2 t = __floats2half2_rn(a, b);
    return *(uint32_t*)&t;
}

__device__ __forceinline__ uint32_t sw128(int r, int c16) {
    return (uint32_t)(r * 128 + ((c16 ^ (r & 7)) << 4));
}
__device__ __forceinline__ uint32_t sw256(int r, int c16) {
    return (uint32_t)(r * 256 + ((c16 ^ (r & 7)) << 4));
}

// ---------------------------------------------------------------------------
// GEMM: fp16 1-product, 3-stage cp.async, M-offset for partial launches.
// ---------------------------------------------------------------------------
#define G1P_STAGE 49152
#define G1P_SMEM (3 * G1P_STAGE)
template <typename OutT, bool QPERM>
__global__ __launch_bounds__(256, 1)
void gemm_mma_kernel(const __half* __restrict__ Ahi, const __half* __restrict__ Bhi,
                     const float* __restrict__ bias, OutT* __restrict__ C,
                     int M, int N, int K, int yoff) {
    extern __shared__ char smraw[];
    const uint32_t sbase = smem_u32(smraw);
    const int tid = threadIdx.x;
    const int lane = tid & 31;
    const int warp = tid >> 5;
    const int wm = warp >> 1;
    const int wn = warp & 1;

    const int row0 = (blockIdx.y + yoff) * 256;
    const int col0 = blockIdx.x * 128;
    const __half* pAhi = Ahi + (size_t)row0 * K;
    const __half* pBhi = Bhi + (size_t)col0 * K;
    const int nk = K / 64;

    auto load_stage = [&](int kc, int st) {
        const int kbase = kc * 64;
        const uint32_t stg = sbase + st * G1P_STAGE;
#pragma unroll
        for (int it = 0; it < 8; it++) {
            int idx = tid + it * 256;
            int r = idx >> 3, c = idx & 7;
            CP_ASYNC16(stg + sw128(r, c), pAhi + (size_t)r * K + kbase + c * 8);
        }
#pragma unroll
        for (int it = 0; it < 4; it++) {
            int idx = tid + it * 256;
            int r = idx >> 3, c = idx & 7;
            CP_ASYNC16(stg + 32768 + sw128(r, c), pBhi + (size_t)r * K + kbase + c * 8);
        }
    };

    float acc[4][8][4];
#pragma unroll
    for (int i = 0; i < 4; i++)
#pragma unroll
        for (int j = 0; j < 8; j++)
#pragma unroll
            for (int k = 0; k < 4; k++) acc[i][j][k] = 0.f;

    load_stage(0, 0); CP_COMMIT();
    load_stage(1, 1); CP_COMMIT();

    for (int kc = 0; kc < nk; kc++) {
        if (kc == nk - 1) { CP_WAIT0(); } else { CP_WAIT1(); }
        __syncthreads();
        if (kc + 2 < nk) {
            load_stage(kc + 2, (kc + 2) % 3);
            CP_COMMIT();
        }

        const uint32_t stg = sbase + (kc % 3) * G1P_STAGE;
        const uint32_t sAhi = stg, sBhi = stg + 32768;

#pragma unroll
        for (int ks = 0; ks < 4; ks++) {
            const int arow = wm * 64 + (lane & 15);
            const int ac = ks * 2 + (lane >> 4);
            const int brow = wn * 64 + (lane & 7);
            const int bc = ks * 2 + ((lane >> 3) & 1);

            uint32_t ah[4][4], bf[8][2];
#pragma unroll
            for (int mt = 0; mt < 4; mt++)
                LDSM4(ah[mt][0], ah[mt][1], ah[mt][2], ah[mt][3],
                      sAhi + sw128(arow + mt * 16, ac));
#pragma unroll
            for (int nt = 0; nt < 8; nt++)
                LDSM2(bf[nt][0], bf[nt][1], sBhi + sw128(brow + nt * 8, bc));
#pragma unroll
            for (int mt = 0; mt < 4; mt++)
#pragma unroll
                for (int nt = 0; nt < 8; nt++)
                    mma16816h(acc[mt][nt], ah[mt], bf[nt]);
        }
    }

#pragma unroll
    for (int mt = 0; mt < 4; mt++) {
        int r = row0 + wm * 64 + mt * 16 + (lane >> 2);
#pragma unroll
        for (int nt = 0; nt < 8; nt++) {
            int c = col0 + wn * 64 + nt * 8 + (lane & 3) * 2;
            if constexpr (QPERM) {
                int h = c >> 8, dd = (c >> 6) & 3, v = c & 63;
                int b = r >> 9, s = r & 511;
                float b0 = __ldg(bias + dd * 1024 + v * 16 + h);
                float b1 = __ldg(bias + dd * 1024 + (v + 1) * 16 + h);
                size_t dst0 = ((size_t)(b * 16 + h) * SDUP + (s * 4 + dd)) * VECD + v;
                size_t dst1 = ((size_t)(b * 16 + h) * SDUP + ((s + 8) * 4 + dd)) * VECD + v;
                *(__half2*)((__half*)C + dst0) =
                    __floats2half2_rn(acc[mt][nt][0] + b0, acc[mt][nt][1] + b1);
                *(__half2*)((__half*)C + dst1) =
                    __floats2half2_rn(acc[mt][nt][2] + b0, acc[mt][nt][3] + b1);
            } else {
                float b0 = __ldg(bias + c), b1 = __ldg(bias + c + 1);
                *(float2*)((float*)C + (size_t)r * N + c) =
                    make_float2(acc[mt][nt][0] + b0, acc[mt][nt][1] + b1);
                *(float2*)((float*)C + (size_t)(r + 8) * N + c) =
                    make_float2(acc[mt][nt][2] + b0, acc[mt][nt][3] + b1);
            }
        }
    }
}

// ---------------------------------------------------------------------------
// fp32 -> fp16 convert (plain)
// ---------------------------------------------------------------------------
__global__ __launch_bounds__(256)
void conv16_kernel(const float4* __restrict__ x, __half2* __restrict__ hi, int n4) {
    int i = blockIdx.x * 256 + threadIdx.x;
    if (i >= n4) return;
    float4 v = x[i];
    hi[2 * i] = __floats2half2_rn(v.x, v.y);
    hi[2 * i + 1] = __floats2half2_rn(v.z, v.w);
}

// fp32 -> fp16 Wq with row permutation
__global__ __launch_bounds__(256)
void convq_kernel(const float* __restrict__ Wq, __half* __restrict__ wqp) {
    int np = blockIdx.x;
    int h = np >> 8, dd = (np >> 6) & 3, v = np & 63;
    int j = dd * 1024 + v * 16 + h;
    const float4* src = (const float4*)(Wq + (size_t)j * HID);
    __half2* dst = (__half2*)(wqp + (size_t)np * HID);
    int tid = threadIdx.x;
#pragma unroll
    for (int it = 0; it < 4; it++) {
        int i = tid + it * 256;
        float4 x = src[i];
        dst[2 * i] = __floats2half2_rn(x.x, x.y);
        dst[2 * i + 1] = __floats2half2_rn(x.z, x.w);
    }
}

// ---------------------------------------------------------------------------
// KV prep (unchanged)
// ---------------------------------------------------------------------------
#define KVP_SMEM (2 * 4 * 1024 * 4)
__global__ __launch_bounds__(256)
void kvprep_kernel(const float* __restrict__ keys, const float* __restrict__ vals,
                   __half* __restrict__ khi, __half* __restrict__ vhi) {
    extern __shared__ float smf[];
    float* sk = smf;
    float* sv = smf + 4 * 1024;
    const int bid = blockIdx.x;
    const int b = bid >> 7, nc = bid & 127;
    const int n0 = nc * 4;
    const int tid = threadIdx.x;

    const float* ksrc = keys + ((size_t)b * NKV + n0) * 1024;
    const float* vsrc = vals + ((size_t)b * NKV + n0) * 1024;
#pragma unroll
    for (int it = 0; it < 4; it++) {
        int i = tid + it * 256;
        *(float4*)&sk[i * 4] = *(const float4*)(ksrc + i * 4);
        *(float4*)&sv[i * 4] = *(const float4*)(vsrc + i * 4);
    }
    __syncthreads();

#pragma unroll
    for (int it = 0; it < 2; it++) {
        int task = tid + it * 256;
        int vg = task & 7, n = (task >> 3) & 3, h = task >> 5;
        uint32_t hhx[4];
#pragma unroll
        for (int j = 0; j < 4; j++) {
            float x0 = sk[n * 1024 + (vg * 8 + j * 2 + 0) * 16 + h];
            float x1 = sk[n * 1024 + (vg * 8 + j * 2 + 1) * 16 + h];
            hhx[j] = pack_h2(x0, x1);
        }
        size_t dst = ((size_t)(b * 16 + h) * NKV + n0 + n) * VECD + vg * 8;
        *(uint4*)(khi + dst) = make_uint4(hhx[0], hhx[1], hhx[2], hhx[3]);
    }

#pragma unroll
    for (int it = 0; it < 4; it++) {
        int task = tid + it * 256;
        int v = task & 63, h = task >> 6;
        uint32_t p0 = pack_h2(sv[0 * 1024 + v * 16 + h], sv[1 * 1024 + v * 16 + h]);
        uint32_t p1 = pack_h2(sv[2 * 1024 + v * 16 + h], sv[3 * 1024 + v * 16 + h]);
        size_t dst = ((size_t)(b * 16 + h) * VECD + v) * NKV + n0;
        *(uint2*)(vhi + dst) = make_uint2(p0, p1);
    }
}

// ---------------------------------------------------------------------------
// Flash attention: fp32 exp2f P, fp16 output, bh offset.
// ---------------------------------------------------------------------------
#define ATT_SMEM (16384 + 2 * 32768)
#define LOG2E 1.4426950408889634f
__global__ __launch_bounds__(256)
void attn_mma_kernel(const __half* __restrict__ qhi,
                     const __half* __restrict__ khi, const __half* __restrict__ vhi,
                     __half* __restrict__ outT, int bhoff) {
    extern __shared__ char smraw[];
    const uint32_t sQ = smem_u32(smraw);
    const uint32_t sKV = sQ + 16384;

    const int tid = threadIdx.x;
    const int lane = tid & 31;
    const int warp = tid >> 5;
    const int g = lane >> 2;
    const int tq = lane & 3;
    const int bh = blockIdx.y + bhoff;
    const int tile = blockIdx.x;
    const int wrow0 = warp * 16;

    const __half* qh = qhi + ((size_t)bh * SDUP + tile * 128) * VECD;
    const __half* kh = khi + (size_t)bh * NKV * VECD;
    const __half* vh = vhi + (size_t)bh * VECD * NKV;

    auto load_kv = [&](int ck, int buf) {
        const int n0 = ck * 128;
        const uint32_t sK = sKV + buf * 32768;
        const uint32_t sV = sK + 16384;
#pragma unroll
        for (int it = 0; it < 4; it++) {
            int idx = tid + it * 256;
            int r = idx >> 3, c = idx & 7;
            CP_ASYNC16(sK + sw128(r, c), kh + (size_t)(n0 + r) * VECD + c * 8);
            int v = idx >> 4, cc = idx & 15;
            CP_ASYNC16(sV + sw256(v, cc), vh + (size_t)v * NKV + n0 + cc * 8);
        }
    };

#pragma unroll
    for (int it = 0; it < 4; it++) {
        int idx = tid + it * 256;
        int r = idx >> 3, c = idx & 7;
        CP_ASYNC16(sQ + sw128(r, c), qh + (size_t)r * VECD + c * 8);
    }
    load_kv(0, 0);
    CP_COMMIT();

    float oa[8][4];
#pragma unroll
    for (int i = 0; i < 8; i++)
#pragma unroll
        for (int j = 0; j < 4; j++) oa[i][j] = 0.f;
    float m0 = -1e30f, m1 = -1e30f, l0 = 0.f, l1 = 0.f;

    for (int ck = 0; ck < 4; ck++) {
        CP_WAIT0();
        __syncthreads();
        if (ck < 3) {
            load_kv(ck + 1, (ck + 1) & 1);
            CP_COMMIT();
        }
        const uint32_t sK = sKV + (ck & 1) * 32768;
        const uint32_t sV = sK + 16384;

        float S[16][4];
#pragma unroll
        for (int jt = 0; jt < 16; jt++)
#pragma unroll
            for (int j = 0; j < 4; j++) S[jt][j] = 0.f;

#pragma unroll
        for (int ks = 0; ks < 4; ks++) {
            uint32_t ah[4];
            int arow = wrow0 + (lane & 15);
            int ac = ks * 2 + (lane >> 4);
            LDSM4(ah[0], ah[1], ah[2], ah[3], sQ + sw128(arow, ac));
#pragma unroll
            for (int jt = 0; jt < 16; jt++) {
                int brow = jt * 8 + (lane & 7);
                int bc = ks * 2 + ((lane >> 3) & 1);
                uint32_t b2[2];
                LDSM2(b2[0], b2[1], sK + sw128(brow, bc));
                mma16816h(S[jt], ah, b2);
            }
        }

        float cm0 = -1e30f, cm1 = -1e30f;
#pragma unroll
        for (int jt = 0; jt < 16; jt++) {
            S[jt][0] *= 0.125f * LOG2E; S[jt][1] *= 0.125f * LOG2E;
            S[jt][2] *= 0.125f * LOG2E; S[jt][3] *= 0.125f * LOG2E;
            cm0 = fmaxf(cm0, fmaxf(S[jt][0], S[jt][1]));
            cm1 = fmaxf(cm1, fmaxf(S[jt][2], S[jt][3]));
        }
        cm0 = fmaxf(cm0, __shfl_xor_sync(0xffffffffu, cm0, 1));
        cm0 = fmaxf(cm0, __shfl_xor_sync(0xffffffffu, cm0, 2));
        cm1 = fmaxf(cm1, __shfl_xor_sync(0xffffffffu, cm1, 1));
        cm1 = fmaxf(cm1, __shfl_xor_sync(0xffffffffu, cm1, 2));
        float mn0 = fmaxf(m0, cm0), mn1 = fmaxf(m1, cm1);
        float sc0 = exp2f(m0 - mn0), sc1 = exp2f(m1 - mn1);
        m0 = mn0; m1 = mn1;
        l0 *= sc0; l1 *= sc1;
#pragma unroll
        for (int vt = 0; vt < 8; vt++) {
            oa[vt][0] *= sc0; oa[vt][1] *= sc0;
            oa[vt][2] *= sc1; oa[vt][3] *= sc1;
        }

        float cs0 = 0.f, cs1 = 0.f;
#pragma unroll
        for (int ks = 0; ks < 8; ks++) {
            uint32_t pah[4];
#pragma unroll
            for (int half = 0; half < 2; half++) {
                int jt = ks * 2 + half;
                float p0 = exp2f(S[jt][0] - m0);
                float p1 = exp2f(S[jt][1] - m0);
                float p2 = exp2f(S[jt][2] - m1);
                float p3 = exp2f(S[jt][3] - m1);
                cs0 += p0 + p1;
                cs1 += p2 + p3;
                pah[half * 2 + 0] = pack_h2(p0, p1);
                pah[half * 2 + 1] = pack_h2(p2, p3);
            }
#pragma unroll
            for (int vt = 0; vt < 8; vt++) {
                int brow = vt * 8 + (lane & 7);
                int bc = ks * 2 + ((lane >> 3) & 1);
                uint32_t b2[2];
                LDSM2(b2[0], b2[1], sV + sw256(brow, bc));
                mma16816h(oa[vt], pah, b2);
            }
        }
        cs0 += __shfl_xor_sync(0xffffffffu, cs0, 1);
        cs0 += __shfl_xor_sync(0xffffffffu, cs0, 2);
        cs1 += __shfl_xor_sync(0xffffffffu, cs1, 1);
        cs1 += __shfl_xor_sync(0xffffffffu, cs1, 2);
        l0 += cs0; l1 += cs1;
    }

    float inv0 = 1.f / l0, inv1 = 1.f / l1;
    __half* orow0 = outT + ((size_t)bh * SDUP + tile * 128 + wrow0 + g) * VECD;
    __half* orow1 = orow0 + 8 * VECD;
#pragma unroll
    for (int vt = 0; vt < 8; vt++) {
        int v = vt * 8 + tq * 2;
        *(__half2*)(orow0 + v) = __floats2half2_rn(oa[vt][0] * inv0, oa[vt][1] * inv0);
        *(__half2*)(orow1 + v) = __floats2half2_rn(oa[vt][2] * inv1, oa[vt][3] * inv1);
    }
}

// ---------------------------------------------------------------------------
// LayerNorm: gather fp16 attnT, fp32 stats, fp16 output, row offset.
// ---------------------------------------------------------------------------
__global__ __launch_bounds__(256)
void ln_gather_kernel(const __half* __restrict__ attnT, const float* __restrict__ gam,
                      const float* __restrict__ bet, __half* __restrict__ hi, int roff) {
    __shared__ float xs[HID];
    __shared__ float red[8];
    __shared__ float red2[8];
    const int row = blockIdx.x + roff;
    const int b = row >> 9, s = row & 511;
    const int tid = threadIdx.x;
    const int lane = tid & 31, w = tid >> 5;

    float lsum = 0.f;
#pragma unroll
    for (int it = 0; it < 4; it++) {
        int i = it * 1024 + tid * 4;
        int h = i >> 8, d = (i >> 6) & 3, v = i & 63;
        const __half* src = attnT + ((size_t)(b * 16 + h) * SDUP + (s * 4 + d)) * VECD + v;
        uint2 raw = *(const uint2*)src;
        float2 x01 = __half22float2(*(__half2*)&raw.x);
        float2 x23 = __half22float2(*(__half2*)&raw.y);
        xs[i + 0] = x01.x; xs[i + 1] = x01.y;
        xs[i + 2] = x23.x; xs[i + 3] = x23.y;
        lsum += x01.x + x01.y + x23.x + x23.y;
    }
#pragma unroll
    for (int o = 16; o > 0; o >>= 1) lsum += __shfl_xor_sync(0xffffffffu, lsum, o);
    if (lane == 0) red[w] = lsum;
    __syncthreads();
    float tot = 0.f;
#pragma unroll
    for (int j = 0; j < 8; j++) tot += red[j];
    float mu = tot * (1.f / HID);

    float lv = 0.f;
    for (int i = tid; i < HID; i += 256) {
        float d = xs[i] - mu;
        lv += d * d;
    }
#pragma unroll
    for (int o = 16; o > 0; o >>= 1) lv += __shfl_xor_sync(0xffffffffu, lv, o);
    if (lane == 0) red2[w] = lv;
    __syncthreads();
    float tv = 0.f;
#pragma unroll
    for (int j = 0; j < 8; j++) tv += red2[j];
    float inv = rsqrtf(tv * (1.f / HID) + 1e-12f);

#pragma unroll
    for (int it = 0; it < 4; it++) {
        int i = it * 1024 + tid * 4;
        float4 xv = *(const float4*)&xs[i];
        float4 gv = *(const float4*)&gam[i];
        float4 bv = *(const float4*)&bet[i];
        float y0 = (xv.x - mu) * inv * gv.x + bv.x;
        float y1 = (xv.y - mu) * inv * gv.y + bv.y;
        float y2 = (xv.z - mu) * inv * gv.z + bv.z;
        float y3 = (xv.w - mu) * inv * gv.w + bv.w;
        size_t o = (size_t)row * HID + i;
        *(__half2*)(hi + o) = __floats2half2_rn(y0, y1);
        *(__half2*)(hi + o + 2) = __floats2half2_rn(y2, y3);
    }
}

// ---------------------------------------------------------------------------
extern "C" void kernel_launch(void* const* d_in, const int* in_sizes, int n_in,
                              void* d_out, int out_size) {
    const float* emb  = (const float*)d_in[0];
    const float* keys = (const float*)d_in[1];
    const float* vals = (const float*)d_in[2];
    const float* Wq   = (const float*)d_in[3];
    const float* bq   = (const float*)d_in[4];
    const float* Wre  = (const float*)d_in[5];
    const float* bre  = (const float*)d_in[6];
    const float* ln_g = (const float*)d_in[7];
    const float* ln_b = (const float*)d_in[8];
    float* out = (float*)d_out;

    __half *aT, *ehi, *lnhi, *wqp, *wrehi, *qhi, *khi, *vhi;
    cudaGetSymbolAddress((void**)&aT, g_attnT);
    cudaGetSymbolAddress((void**)&ehi, g_ehi);
    cudaGetSymbolAddress((void**)&lnhi, g_lnhi);
    cudaGetSymbolAddress((void**)&wqp, g_wqp);
    cudaGetSymbolAddress((void**)&wrehi, g_wrehi);
    cudaGetSymbolAddress((void**)&qhi, g_qhi);
    cudaGetSymbolAddress((void**)&khi, g_khi);
    cudaGetSymbolAddress((void**)&vhi, g_vhi);

    cudaFuncSetAttribute((const void*)gemm_mma_kernel<__half, true>,
                         cudaFuncAttributeMaxDynamicSharedMemorySize, G1P_SMEM);
    cudaFuncSetAttribute((const void*)gemm_mma_kernel<float, false>,
                         cudaFuncAttributeMaxDynamicSharedMemorySize, G1P_SMEM);
    cudaFuncSetAttribute(attn_mma_kernel, cudaFuncAttributeMaxDynamicSharedMemorySize, ATT_SMEM);
    cudaFuncSetAttribute(kvprep_kernel, cudaFuncAttributeMaxDynamicSharedMemorySize, KVP_SMEM);

    static cudaStream_t sA = nullptr, sB = nullptr;
    static cudaEvent_t evRoot = nullptr, evKV = nullptr, evWq = nullptr, evWre = nullptr;
    static cudaEvent_t evG1[4] = {nullptr, nullptr, nullptr, nullptr};
    static cudaEvent_t evJ0 = nullptr, evJ1 = nullptr, evJ2 = nullptr;
    if (sA == nullptr) {
        cudaStreamCreateWithFlags(&sA, cudaStreamNonBlocking);
        cudaStreamCreateWithFlags(&sB, cudaStreamNonBlocking);
        cudaEventCreateWithFlags(&evRoot, cudaEventDisableTiming);
        cudaEventCreateWithFlags(&evKV, cudaEventDisableTiming);
        cudaEventCreateWithFlags(&evWq, cudaEventDisableTiming);
        cudaEventCreateWithFlags(&evWre, cudaEventDisableTiming);
        for (int i = 0; i < 4; i++)
            cudaEventCreateWithFlags(&evG1[i], cudaEventDisableTiming);
        cudaEventCreateWithFlags(&evJ0, cudaEventDisableTiming);
        cudaEventCreateWithFlags(&evJ1, cudaEventDisableTiming);
        cudaEventCreateWithFlags(&evJ2, cudaEventDisableTiming);
    }

    cudaEventRecord(evRoot, 0);
    cudaStreamWaitEvent(sA, evRoot, 0);
    cudaStreamWaitEvent(sB, evRoot, 0);

    // sA: KV prep (feeds all attention quarters)
    kvprep_kernel<<<4 * 128, 256, KVP_SMEM, sA>>>(keys, vals, khi, vhi);
    cudaEventRecord(evKV, sA);

    // sB: weight conversions
    convq_kernel<<<HID, 256, 0, sB>>>(Wq, wqp);
    cudaEventRecord(evWq, sB);
    conv16_kernel<<<(HID * HID / 4 + 255) / 256, 256, 0, sB>>>(
        (const float4*)Wre, (__half2*)wrehi, HID * HID / 4);
    cudaEventRecord(evWre, sB);

    // main: embeddings -> fp16, then GEMM1 quarters (batch i each)
    conv16_kernel<<<(MROWS * HID / 4 + 255) / 256, 256>>>(
        (const float4*)emb, (__half2*)ehi, MROWS * HID / 4);
    cudaStreamWaitEvent(0, evWq, 0);
    for (int i = 0; i < 4; i++) {
        gemm_mma_kernel<__half, true><<<dim3(HID / 128, 2), 256, G1P_SMEM>>>(
            ehi, wqp, bq, qhi, MROWS, HID, HID, 2 * i);
        cudaEventRecord(evG1[i], 0);
    }

    // sA: chain0 (batch 0), then chain2 (batch 2)
    cudaStreamWaitEvent(sA, evG1[0], 0);
    attn_mma_kernel<<<dim3(16, 16), 256, ATT_SMEM, sA>>>(qhi, khi, vhi, aT, 0);
    ln_gather_kernel<<<512, 256, 0, sA>>>(aT, ln_g, ln_b, lnhi, 0);
    cudaStreamWaitEvent(sA, evWre, 0);
    gemm_mma_kernel<float, false><<<dim3(HID / 128, 2), 256, G1P_SMEM, sA>>>(
        lnhi, wrehi, bre, out, MROWS, HID, HID, 0);
    cudaStreamWaitEvent(sA, evG1[2], 0);
    attn_mma_kernel<<<dim3(16, 16), 256, ATT_SMEM, sA>>>(qhi, khi, vhi, aT, 32);
    ln_gather_kernel<<<512, 256, 0, sA>>>(aT, ln_g, ln_b, lnhi, 1024);
    gemm_mma_kernel<float, false><<<dim3(HID / 128, 2), 256, G1P_SMEM, sA>>>(
        lnhi, wrehi, bre, out, MROWS, HID, HID, 4);
    cudaEventRecord(evJ0, sA);

    // sB: chain1 (batch 1)
    cudaStreamWaitEvent(sB, evKV, 0);
    cudaStreamWaitEvent(sB, evG1[1], 0);
    attn_mma_kernel<<<dim3(16, 16), 256, ATT_SMEM, sB>>>(qhi, khi, vhi, aT, 16);
    ln_gather_kernel<<<512, 256, 0, sB>>>(aT, ln_g, ln_b, lnhi, 512);
    gemm_mma_kernel<float, false><<<dim3(HID / 128, 2), 256, G1P_SMEM, sB>>>(
        lnhi, wrehi, bre, out, MROWS, HID, HID, 2);
    cudaEventRecord(evJ1, sB);

    // main: chain3 (batch 3)
    cudaStreamWaitEvent(0, evKV, 0);
    attn_mma_kernel<<<dim3(16, 16), 256, ATT_SMEM>>>(qhi, khi, vhi, aT, 48);
    ln_gather_kernel<<<512, 256>>>(aT, ln_g, ln_b, lnhi, 1536);
    cudaStreamWaitEvent(0, evWre, 0);
    gemm_mma_kernel<float, false><<<dim3(HID / 128, 2), 256, G1P_SMEM>>>(
        lnhi, wrehi, bre, out, MROWS, HID, HID, 6);

    // join side chains
    cudaStreamWaitEvent(0, evJ0, 0);
    cudaStreamWaitEvent(0, evJ1, 0);
}

// round 17
// speedup vs baseline: 1.1660x; 1.1660x over previous
#include <cuda_runtime.h>
#include <cuda_fp16.h>
#include <cstdint>

#define HID 4096
#define MROWS 2048
#define NKV 512
#define VECD 64
#define NHEAD 16
#define NBH 64
#define SDUP 2048

// ---------------- scratch ----------------
__device__ __half g_attnT[NBH * SDUP * VECD];
__device__ __half g_qhi[NBH * SDUP * VECD];
__device__ __half g_khi[NBH * NKV * VECD];
__device__ __half g_vhi[NBH * VECD * NKV];
__device__ __half g_ehi[MROWS * HID];
__device__ __half g_lnhi[MROWS * HID];
__device__ __half g_wqp[HID * HID];
__device__ __half g_wrehi[HID * HID];

// ---------------- PTX helpers ----------------
__device__ __forceinline__ uint32_t smem_u32(const void* p) {
    uint32_t a;
    asm("{ .reg .u64 t; cvta.to.shared.u64 t, %1; cvt.u32.u64 %0, t; }" : "=r"(a) : "l"(p));
    return a;
}
#define CP_ASYNC16(dst, src) \
    asm volatile("cp.async.cg.shared.global [%0], [%1], 16;" :: "r"(dst), "l"(src))
#define CP_COMMIT() asm volatile("cp.async.commit_group;" ::: "memory")
#define CP_WAIT0()  asm volatile("cp.async.wait_group 0;" ::: "memory")
#define CP_WAIT1()  asm volatile("cp.async.wait_group 1;" ::: "memory")

#define LDSM4(r0, r1, r2, r3, addr)                                          \
    asm volatile("ldmatrix.sync.aligned.m8n8.x4.shared.b16 {%0,%1,%2,%3}, [%4];" \
                 : "=r"(r0), "=r"(r1), "=r"(r2), "=r"(r3) : "r"(addr))
#define LDSM2(r0, r1, addr)                                                  \
    asm volatile("ldmatrix.sync.aligned.m8n8.x2.shared.b16 {%0,%1}, [%2];"   \
                 : "=r"(r0), "=r"(r1) : "r"(addr))

__device__ __forceinline__ void mma16816h(float* c, const uint32_t* a, const uint32_t* b) {
    asm volatile(
        "mma.sync.aligned.m16n8k16.row.col.f32.f16.f16.f32 "
        "{%0,%1,%2,%3}, {%4,%5,%6,%7}, {%8,%9}, {%0,%1,%2,%3};"
        : "+f"(c[0]), "+f"(c[1]), "+f"(c[2]), "+f"(c[3])
        : "r"(a[0]), "r"(a[1]), "r"(a[2]), "r"(a[3]), "r"(b[0]), "r"(b[1]));
}

__device__ __forceinline__ uint32_t pack_h2(float a, float b) {
    __half2 t = __floats2half2_rn(a, b);
    return *(uint32_t*)&t;
}

__device__ __forceinline__ uint32_t sw128(int r, int c16) {
    return (uint32_t)(r * 128 + ((c16 ^ (r & 7)) << 4));
}
__device__ __forceinline__ uint32_t sw256(int r, int c16) {
    return (uint32_t)(r * 256 + ((c16 ^ (r & 7)) << 4));
}

// ---------------------------------------------------------------------------
// GEMM: fp16 1-product, 3-stage cp.async, M-offset for half launches.
// ---------------------------------------------------------------------------
#define G1P_STAGE 49152
#define G1P_SMEM (3 * G1P_STAGE)
template <typename OutT, bool QPERM>
__global__ __launch_bounds__(256, 1)
void gemm_mma_kernel(const __half* __restrict__ Ahi, const __half* __restrict__ Bhi,
                     const float* __restrict__ bias, OutT* __restrict__ C,
                     int M, int N, int K, int yoff) {
    extern __shared__ char smraw[];
    const uint32_t sbase = smem_u32(smraw);
    const int tid = threadIdx.x;
    const int lane = tid & 31;
    const int warp = tid >> 5;
    const int wm = warp >> 1;
    const int wn = warp & 1;

    const int row0 = (blockIdx.y + yoff) * 256;
    const int col0 = blockIdx.x * 128;
    const __half* pAhi = Ahi + (size_t)row0 * K;
    const __half* pBhi = Bhi + (size_t)col0 * K;
    const int nk = K / 64;

    auto load_stage = [&](int kc, int st) {
        const int kbase = kc * 64;
        const uint32_t stg = sbase + st * G1P_STAGE;
#pragma unroll
        for (int it = 0; it < 8; it++) {
            int idx = tid + it * 256;
            int r = idx >> 3, c = idx & 7;
            CP_ASYNC16(stg + sw128(r, c), pAhi + (size_t)r * K + kbase + c * 8);
        }
#pragma unroll
        for (int it = 0; it < 4; it++) {
            int idx = tid + it * 256;
            int r = idx >> 3, c = idx & 7;
            CP_ASYNC16(stg + 32768 + sw128(r, c), pBhi + (size_t)r * K + kbase + c * 8);
        }
    };

    float acc[4][8][4];
#pragma unroll
    for (int i = 0; i < 4; i++)
#pragma unroll
        for (int j = 0; j < 8; j++)
#pragma unroll
            for (int k = 0; k < 4; k++) acc[i][j][k] = 0.f;

    load_stage(0, 0); CP_COMMIT();
    load_stage(1, 1); CP_COMMIT();

    for (int kc = 0; kc < nk; kc++) {
        if (kc == nk - 1) { CP_WAIT0(); } else { CP_WAIT1(); }
        __syncthreads();
        if (kc + 2 < nk) {
            load_stage(kc + 2, (kc + 2) % 3);
            CP_COMMIT();
        }

        const uint32_t stg = sbase + (kc % 3) * G1P_STAGE;
        const uint32_t sAhi = stg, sBhi = stg + 32768;

#pragma unroll
        for (int ks = 0; ks < 4; ks++) {
            const int arow = wm * 64 + (lane & 15);
            const int ac = ks * 2 + (lane >> 4);
            const int brow = wn * 64 + (lane & 7);
            const int bc = ks * 2 + ((lane >> 3) & 1);

            uint32_t ah[4][4], bf[8][2];
#pragma unroll
            for (int mt = 0; mt < 4; mt++)
                LDSM4(ah[mt][0], ah[mt][1], ah[mt][2], ah[mt][3],
                      sAhi + sw128(arow + mt * 16, ac));
#pragma unroll
            for (int nt = 0; nt < 8; nt++)
                LDSM2(bf[nt][0], bf[nt][1], sBhi + sw128(brow + nt * 8, bc));
#pragma unroll
            for (int mt = 0; mt < 4; mt++)
#pragma unroll
                for (int nt = 0; nt < 8; nt++)
                    mma16816h(acc[mt][nt], ah[mt], bf[nt]);
        }
    }

#pragma unroll
    for (int mt = 0; mt < 4; mt++) {
        int r = row0 + wm * 64 + mt * 16 + (lane >> 2);
#pragma unroll
        for (int nt = 0; nt < 8; nt++) {
            int c = col0 + wn * 64 + nt * 8 + (lane & 3) * 2;
            if constexpr (QPERM) {
                int h = c >> 8, dd = (c >> 6) & 3, v = c & 63;
                int b = r >> 9, s = r & 511;
                float b0 = __ldg(bias + dd * 1024 + v * 16 + h);
                float b1 = __ldg(bias + dd * 1024 + (v + 1) * 16 + h);
                size_t dst0 = ((size_t)(b * 16 + h) * SDUP + (s * 4 + dd)) * VECD + v;
                size_t dst1 = ((size_t)(b * 16 + h) * SDUP + ((s + 8) * 4 + dd)) * VECD + v;
                *(__half2*)((__half*)C + dst0) =
                    __floats2half2_rn(acc[mt][nt][0] + b0, acc[mt][nt][1] + b1);
                *(__half2*)((__half*)C + dst1) =
                    __floats2half2_rn(acc[mt][nt][2] + b0, acc[mt][nt][3] + b1);
            } else {
                float b0 = __ldg(bias + c), b1 = __ldg(bias + c + 1);
                *(float2*)((float*)C + (size_t)r * N + c) =
                    make_float2(acc[mt][nt][0] + b0, acc[mt][nt][1] + b1);
                *(float2*)((float*)C + (size_t)(r + 8) * N + c) =
                    make_float2(acc[mt][nt][2] + b0, acc[mt][nt][3] + b1);
            }
        }
    }
}

// ---------------------------------------------------------------------------
// fp32 -> fp16 convert (plain, with element offset)
// ---------------------------------------------------------------------------
__global__ __launch_bounds__(256)
void conv16_kernel(const float4* __restrict__ x, __half2* __restrict__ hi, int n4) {
    int i = blockIdx.x * 256 + threadIdx.x;
    if (i >= n4) return;
    float4 v = x[i];
    hi[2 * i] = __floats2half2_rn(v.x, v.y);
    hi[2 * i + 1] = __floats2half2_rn(v.z, v.w);
}

// fp32 -> fp16 Wq with row permutation
__global__ __launch_bounds__(256)
void convq_kernel(const float* __restrict__ Wq, __half* __restrict__ wqp) {
    int np = blockIdx.x;
    int h = np >> 8, dd = (np >> 6) & 3, v = np & 63;
    int j = dd * 1024 + v * 16 + h;
    const float4* src = (const float4*)(Wq + (size_t)j * HID);
    __half2* dst = (__half2*)(wqp + (size_t)np * HID);
    int tid = threadIdx.x;
#pragma unroll
    for (int it = 0; it < 4; it++) {
        int i = tid + it * 256;
        float4 x = src[i];
        dst[2 * i] = __floats2half2_rn(x.x, x.y);
        dst[2 * i + 1] = __floats2half2_rn(x.z, x.w);
    }
}

// ---------------------------------------------------------------------------
// KV prep (unchanged)
// ---------------------------------------------------------------------------
#define KVP_SMEM (2 * 4 * 1024 * 4)
__global__ __launch_bounds__(256)
void kvprep_kernel(const float* __restrict__ keys, const float* __restrict__ vals,
                   __half* __restrict__ khi, __half* __restrict__ vhi) {
    extern __shared__ float smf[];
    float* sk = smf;
    float* sv = smf + 4 * 1024;
    const int bid = blockIdx.x;
    const int b = bid >> 7, nc = bid & 127;
    const int n0 = nc * 4;
    const int tid = threadIdx.x;

    const float* ksrc = keys + ((size_t)b * NKV + n0) * 1024;
    const float* vsrc = vals + ((size_t)b * NKV + n0) * 1024;
#pragma unroll
    for (int it = 0; it < 4; it++) {
        int i = tid + it * 256;
        *(float4*)&sk[i * 4] = *(const float4*)(ksrc + i * 4);
        *(float4*)&sv[i * 4] = *(const float4*)(vsrc + i * 4);
    }
    __syncthreads();

#pragma unroll
    for (int it = 0; it < 2; it++) {
        int task = tid + it * 256;
        int vg = task & 7, n = (task >> 3) & 3, h = task >> 5;
        uint32_t hhx[4];
#pragma unroll
        for (int j = 0; j < 4; j++) {
            float x0 = sk[n * 1024 + (vg * 8 + j * 2 + 0) * 16 + h];
            float x1 = sk[n * 1024 + (vg * 8 + j * 2 + 1) * 16 + h];
            hhx[j] = pack_h2(x0, x1);
        }
        size_t dst = ((size_t)(b * 16 + h) * NKV + n0 + n) * VECD + vg * 8;
        *(uint4*)(khi + dst) = make_uint4(hhx[0], hhx[1], hhx[2], hhx[3]);
    }

#pragma unroll
    for (int it = 0; it < 4; it++) {
        int task = tid + it * 256;
        int v = task & 63, h = task >> 6;
        uint32_t p0 = pack_h2(sv[0 * 1024 + v * 16 + h], sv[1 * 1024 + v * 16 + h]);
        uint32_t p1 = pack_h2(sv[2 * 1024 + v * 16 + h], sv[3 * 1024 + v * 16 + h]);
        size_t dst = ((size_t)(b * 16 + h) * VECD + v) * NKV + n0;
        *(uint2*)(vhi + dst) = make_uint2(p0, p1);
    }
}

// ---------------------------------------------------------------------------
// Flash attention: fp32 exp2f P, fp16 output, bh offset.
// ---------------------------------------------------------------------------
#define ATT_SMEM (16384 + 2 * 32768)
#define LOG2E 1.4426950408889634f
__global__ __launch_bounds__(256)
void attn_mma_kernel(const __half* __restrict__ qhi,
                     const __half* __restrict__ khi, const __half* __restrict__ vhi,
                     __half* __restrict__ outT, int bhoff) {
    extern __shared__ char smraw[];
    const uint32_t sQ = smem_u32(smraw);
    const uint32_t sKV = sQ + 16384;

    const int tid = threadIdx.x;
    const int lane = tid & 31;
    const int warp = tid >> 5;
    const int g = lane >> 2;
    const int tq = lane & 3;
    const int bh = blockIdx.y + bhoff;
    const int tile = blockIdx.x;
    const int wrow0 = warp * 16;

    const __half* qh = qhi + ((size_t)bh * SDUP + tile * 128) * VECD;
    const __half* kh = khi + (size_t)bh * NKV * VECD;
    const __half* vh = vhi + (size_t)bh * VECD * NKV;

    auto load_kv = [&](int ck, int buf) {
        const int n0 = ck * 128;
        const uint32_t sK = sKV + buf * 32768;
        const uint32_t sV = sK + 16384;
#pragma unroll
        for (int it = 0; it < 4; it++) {
            int idx = tid + it * 256;
            int r = idx >> 3, c = idx & 7;
            CP_ASYNC16(sK + sw128(r, c), kh + (size_t)(n0 + r) * VECD + c * 8);
            int v = idx >> 4, cc = idx & 15;
            CP_ASYNC16(sV + sw256(v, cc), vh + (size_t)v * NKV + n0 + cc * 8);
        }
    };

#pragma unroll
    for (int it = 0; it < 4; it++) {
        int idx = tid + it * 256;
        int r = idx >> 3, c = idx & 7;
        CP_ASYNC16(sQ + sw128(r, c), qh + (size_t)r * VECD + c * 8);
    }
    load_kv(0, 0);
    CP_COMMIT();

    float oa[8][4];
#pragma unroll
    for (int i = 0; i < 8; i++)
#pragma unroll
        for (int j = 0; j < 4; j++) oa[i][j] = 0.f;
    float m0 = -1e30f, m1 = -1e30f, l0 = 0.f, l1 = 0.f;

    for (int ck = 0; ck < 4; ck++) {
        CP_WAIT0();
        __syncthreads();
        if (ck < 3) {
            load_kv(ck + 1, (ck + 1) & 1);
            CP_COMMIT();
        }
        const uint32_t sK = sKV + (ck & 1) * 32768;
        const uint32_t sV = sK + 16384;

        float S[16][4];
#pragma unroll
        for (int jt = 0; jt < 16; jt++)
#pragma unroll
            for (int j = 0; j < 4; j++) S[jt][j] = 0.f;

#pragma unroll
        for (int ks = 0; ks < 4; ks++) {
            uint32_t ah[4];
            int arow = wrow0 + (lane & 15);
            int ac = ks * 2 + (lane >> 4);
            LDSM4(ah[0], ah[1], ah[2], ah[3], sQ + sw128(arow, ac));
#pragma unroll
            for (int jt = 0; jt < 16; jt++) {
                int brow = jt * 8 + (lane & 7);
                int bc = ks * 2 + ((lane >> 3) & 1);
                uint32_t b2[2];
                LDSM2(b2[0], b2[1], sK + sw128(brow, bc));
                mma16816h(S[jt], ah, b2);
            }
        }

        float cm0 = -1e30f, cm1 = -1e30f;
#pragma unroll
        for (int jt = 0; jt < 16; jt++) {
            S[jt][0] *= 0.125f * LOG2E; S[jt][1] *= 0.125f * LOG2E;
            S[jt][2] *= 0.125f * LOG2E; S[jt][3] *= 0.125f * LOG2E;
            cm0 = fmaxf(cm0, fmaxf(S[jt][0], S[jt][1]));
            cm1 = fmaxf(cm1, fmaxf(S[jt][2], S[jt][3]));
        }
        cm0 = fmaxf(cm0, __shfl_xor_sync(0xffffffffu, cm0, 1));
        cm0 = fmaxf(cm0, __shfl_xor_sync(0xffffffffu, cm0, 2));
        cm1 = fmaxf(cm1, __shfl_xor_sync(0xffffffffu, cm1, 1));
        cm1 = fmaxf(cm1, __shfl_xor_sync(0xffffffffu, cm1, 2));
        float mn0 = fmaxf(m0, cm0), mn1 = fmaxf(m1, cm1);
        float sc0 = exp2f(m0 - mn0), sc1 = exp2f(m1 - mn1);
        m0 = mn0; m1 = mn1;
        l0 *= sc0; l1 *= sc1;
#pragma unroll
        for (int vt = 0; vt < 8; vt++) {
            oa[vt][0] *= sc0; oa[vt][1] *= sc0;
            oa[vt][2] *= sc1; oa[vt][3] *= sc1;
        }

        float cs0 = 0.f, cs1 = 0.f;
#pragma unroll
        for (int ks = 0; ks < 8; ks++) {
            uint32_t pah[4];
#pragma unroll
            for (int half = 0; half < 2; half++) {
                int jt = ks * 2 + half;
                float p0 = exp2f(S[jt][0] - m0);
                float p1 = exp2f(S[jt][1] - m0);
                float p2 = exp2f(S[jt][2] - m1);
                float p3 = exp2f(S[jt][3] - m1);
                cs0 += p0 + p1;
                cs1 += p2 + p3;
                pah[half * 2 + 0] = pack_h2(p0, p1);
                pah[half * 2 + 1] = pack_h2(p2, p3);
            }
#pragma unroll
            for (int vt = 0; vt < 8; vt++) {
                int brow = vt * 8 + (lane & 7);
                int bc = ks * 2 + ((lane >> 3) & 1);
                uint32_t b2[2];
                LDSM2(b2[0], b2[1], sV + sw256(brow, bc));
                mma16816h(oa[vt], pah, b2);
            }
        }
        cs0 += __shfl_xor_sync(0xffffffffu, cs0, 1);
        cs0 += __shfl_xor_sync(0xffffffffu, cs0, 2);
        cs1 += __shfl_xor_sync(0xffffffffu, cs1, 1);
        cs1 += __shfl_xor_sync(0xffffffffu, cs1, 2);
        l0 += cs0; l1 += cs1;
    }

    float inv0 = 1.f / l0, inv1 = 1.f / l1;
    __half* orow0 = outT + ((size_t)bh * SDUP + tile * 128 + wrow0 + g) * VECD;
    __half* orow1 = orow0 + 8 * VECD;
#pragma unroll
    for (int vt = 0; vt < 8; vt++) {
        int v = vt * 8 + tq * 2;
        *(__half2*)(orow0 + v) = __floats2half2_rn(oa[vt][0] * inv0, oa[vt][1] * inv0);
        *(__half2*)(orow1 + v) = __floats2half2_rn(oa[vt][2] * inv1, oa[vt][3] * inv1);
    }
}

// ---------------------------------------------------------------------------
// LayerNorm: gather fp16 attnT, fp32 stats, fp16 output, row offset.
// ---------------------------------------------------------------------------
__global__ __launch_bounds__(256)
void ln_gather_kernel(const __half* __restrict__ attnT, const float* __restrict__ gam,
                      const float* __restrict__ bet, __half* __restrict__ hi, int roff) {
    __shared__ float xs[HID];
    __shared__ float red[8];
    __shared__ float red2[8];
    const int row = blockIdx.x + roff;
    const int b = row >> 9, s = row & 511;
    const int tid = threadIdx.x;
    const int lane = tid & 31, w = tid >> 5;

    float lsum = 0.f;
#pragma unroll
    for (int it = 0; it < 4; it++) {
        int i = it * 1024 + tid * 4;
        int h = i >> 8, d = (i >> 6) & 3, v = i & 63;
        const __half* src = attnT + ((size_t)(b * 16 + h) * SDUP + (s * 4 + d)) * VECD + v;
        uint2 raw = *(const uint2*)src;
        float2 x01 = __half22float2(*(__half2*)&raw.x);
        float2 x23 = __half22float2(*(__half2*)&raw.y);
        xs[i + 0] = x01.x; xs[i + 1] = x01.y;
        xs[i + 2] = x23.x; xs[i + 3] = x23.y;
        lsum += x01.x + x01.y + x23.x + x23.y;
    }
#pragma unroll
    for (int o = 16; o > 0; o >>= 1) lsum += __shfl_xor_sync(0xffffffffu, lsum, o);
    if (lane == 0) red[w] = lsum;
    __syncthreads();
    float tot = 0.f;
#pragma unroll
    for (int j = 0; j < 8; j++) tot += red[j];
    float mu = tot * (1.f / HID);

    float lv = 0.f;
    for (int i = tid; i < HID; i += 256) {
        float d = xs[i] - mu;
        lv += d * d;
    }
#pragma unroll
    for (int o = 16; o > 0; o >>= 1) lv += __shfl_xor_sync(0xffffffffu, lv, o);
    if (lane == 0) red2[w] = lv;
    __syncthreads();
    float tv = 0.f;
#pragma unroll
    for (int j = 0; j < 8; j++) tv += red2[j];
    float inv = rsqrtf(tv * (1.f / HID) + 1e-12f);

#pragma unroll
    for (int it = 0; it < 4; it++) {
        int i = it * 1024 + tid * 4;
        float4 xv = *(const float4*)&xs[i];
        float4 gv = *(const float4*)&gam[i];
        float4 bv = *(const float4*)&bet[i];
        float y0 = (xv.x - mu) * inv * gv.x + bv.x;
        float y1 = (xv.y - mu) * inv * gv.y + bv.y;
        float y2 = (xv.z - mu) * inv * gv.z + bv.z;
        float y3 = (xv.w - mu) * inv * gv.w + bv.w;
        size_t o = (size_t)row * HID + i;
        *(__half2*)(hi + o) = __floats2half2_rn(y0, y1);
        *(__half2*)(hi + o + 2) = __floats2half2_rn(y2, y3);
    }
}

// ---------------------------------------------------------------------------
extern "C" void kernel_launch(void* const* d_in, const int* in_sizes, int n_in,
                              void* d_out, int out_size) {
    const float* emb  = (const float*)d_in[0];
    const float* keys = (const float*)d_in[1];
    const float* vals = (const float*)d_in[2];
    const float* Wq   = (const float*)d_in[3];
    const float* bq   = (const float*)d_in[4];
    const float* Wre  = (const float*)d_in[5];
    const float* bre  = (const float*)d_in[6];
    const float* ln_g = (const float*)d_in[7];
    const float* ln_b = (const float*)d_in[8];
    float* out = (float*)d_out;

    __half *aT, *ehi, *lnhi, *wqp, *wrehi, *qhi, *khi, *vhi;
    cudaGetSymbolAddress((void**)&aT, g_attnT);
    cudaGetSymbolAddress((void**)&ehi, g_ehi);
    cudaGetSymbolAddress((void**)&lnhi, g_lnhi);
    cudaGetSymbolAddress((void**)&wqp, g_wqp);
    cudaGetSymbolAddress((void**)&wrehi, g_wrehi);
    cudaGetSymbolAddress((void**)&qhi, g_qhi);
    cudaGetSymbolAddress((void**)&khi, g_khi);
    cudaGetSymbolAddress((void**)&vhi, g_vhi);

    cudaFuncSetAttribute((const void*)gemm_mma_kernel<__half, true>,
                         cudaFuncAttributeMaxDynamicSharedMemorySize, G1P_SMEM);
    cudaFuncSetAttribute((const void*)gemm_mma_kernel<float, false>,
                         cudaFuncAttributeMaxDynamicSharedMemorySize, G1P_SMEM);
    cudaFuncSetAttribute(attn_mma_kernel, cudaFuncAttributeMaxDynamicSharedMemorySize, ATT_SMEM);
    cudaFuncSetAttribute(kvprep_kernel, cudaFuncAttributeMaxDynamicSharedMemorySize, KVP_SMEM);

    static cudaStream_t sA = nullptr, sB = nullptr;
    static cudaEvent_t evRoot = nullptr, evKV = nullptr, evWq = nullptr, evWre = nullptr;
    static cudaEvent_t evG1a = nullptr, evEB = nullptr, evJoin = nullptr;
    if (sA == nullptr) {
        cudaStreamCreateWithFlags(&sA, cudaStreamNonBlocking);
        cudaStreamCreateWithFlags(&sB, cudaStreamNonBlocking);
        cudaEventCreateWithFlags(&evRoot, cudaEventDisableTiming);
        cudaEventCreateWithFlags(&evKV, cudaEventDisableTiming);
        cudaEventCreateWithFlags(&evWq, cudaEventDisableTiming);
        cudaEventCreateWithFlags(&evWre, cudaEventDisableTiming);
        cudaEventCreateWithFlags(&evG1a, cudaEventDisableTiming);
        cudaEventCreateWithFlags(&evEB, cudaEventDisableTiming);
        cudaEventCreateWithFlags(&evJoin, cudaEventDisableTiming);
    }

    const int HALF4 = MROWS * HID / 8;    // float4 count per emb half

    cudaEventRecord(evRoot, 0);
    cudaStreamWaitEvent(sA, evRoot, 0);
    cudaStreamWaitEvent(sB, evRoot, 0);

    // sA: KV prep, then emb half B convert
    kvprep_kernel<<<4 * 128, 256, KVP_SMEM, sA>>>(keys, vals, khi, vhi);
    cudaEventRecord(evKV, sA);
    conv16_kernel<<<(HALF4 + 255) / 256, 256, 0, sA>>>(
        (const float4*)emb + HALF4, (__half2*)ehi + 2 * (size_t)HALF4, HALF4);
    cudaEventRecord(evEB, sA);

    // sB: weight conversions
    convq_kernel<<<HID, 256, 0, sB>>>(Wq, wqp);
    cudaEventRecord(evWq, sB);
    conv16_kernel<<<(HID * HID / 4 + 255) / 256, 256, 0, sB>>>(
        (const float4*)Wre, (__half2*)wrehi, HID * HID / 4);
    cudaEventRecord(evWre, sB);

    // main: emb half A convert -> GEMM1 half A (batches 0,1)
    conv16_kernel<<<(HALF4 + 255) / 256, 256>>>(
        (const float4*)emb, (__half2*)ehi, HALF4);
    cudaStreamWaitEvent(0, evWq, 0);
    gemm_mma_kernel<__half, true><<<dim3(HID / 128, 4), 256, G1P_SMEM>>>(
        ehi, wqp, bq, qhi, MROWS, HID, HID, 0);
    cudaEventRecord(evG1a, 0);
    // main: GEMM1 half B (batches 2,3) — needs emb half B
    cudaStreamWaitEvent(0, evEB, 0);
    gemm_mma_kernel<__half, true><<<dim3(HID / 128, 4), 256, G1P_SMEM>>>(
        ehi, wqp, bq, qhi, MROWS, HID, HID, 4);

    // sA half-chain: attn(bh 0..31) -> ln(rows 0..1023) -> GEMM2 half A
    cudaStreamWaitEvent(sA, evG1a, 0);
    attn_mma_kernel<<<dim3(16, 32), 256, ATT_SMEM, sA>>>(qhi, khi, vhi, aT, 0);
    ln_gather_kernel<<<1024, 256, 0, sA>>>(aT, ln_g, ln_b, lnhi, 0);
    cudaStreamWaitEvent(sA, evWre, 0);
    gemm_mma_kernel<float, false><<<dim3(HID / 128, 4), 256, G1P_SMEM, sA>>>(
        lnhi, wrehi, bre, out, MROWS, HID, HID, 0);
    cudaEventRecord(evJoin, sA);

    // main half-chain: attn(bh 32..63) -> ln(rows 1024..2047) -> GEMM2 half B
    cudaStreamWaitEvent(0, evKV, 0);
    attn_mma_kernel<<<dim3(16, 32), 256, ATT_SMEM>>>(qhi, khi, vhi, aT, 32);
    ln_gather_kernel<<<1024, 256>>>(aT, ln_g, ln_b, lnhi, 1024);
    cudaStreamWaitEvent(0, evWre, 0);
    gemm_mma_kernel<float, false><<<dim3(HID / 128, 4), 256, G1P_SMEM>>>(
        lnhi, wrehi, bre, out, MROWS, HID, HID, 4);

    // join sA back into main
    cudaStreamWaitEvent(0, evJoin, 0);
}